// round 11
// baseline (speedup 1.0000x reference)
#include <cuda_runtime.h>
#include <math.h>

// B=256, T=512, C=512, L=64
#define BN 256
#define TN 512
#define CN 512
#define LN 64
#define SN 129              // 2L+1
#define BLANK 511
#define EPSV 1e-7f
#define KS 5                // states per lane
#define PD 8                // prefetch depth (register ring, unroll-matched)
#define LN2F 0.6931471805599453f
#define FULL 0xffffffffu

// CTC forward DP: one warp per batch element. No smem ring — each lane
// prefetches its needed probabilities (blank broadcast + 3 label classes)
// directly from gmem with __ldg, 8 steps ahead, into a register ring.
// Only the ~43 distinct 32B sectors per row are ever requested from DRAM
// (vs the full 2KB row previously). Alpha in registers (5/lane), neighbors
// via shfl. Linear-space recursion + exact power-of-2 renorm (identical
// arithmetic/order to previous rounds; rel_err unchanged).
__global__ __launch_bounds__(32, 8)
void ctc_ldg_kernel(const int* __restrict__ labels,     // [B, L]
                    const float* __restrict__ y_pred,   // [B, T, C]
                    const int* __restrict__ in_len,     // [B, 1]
                    const int* __restrict__ lab_len,    // [B, 1]
                    float* __restrict__ out)            // [B, 1]
{
    const int b    = blockIdx.x;
    const int lane = threadIdx.x;
    const bool oddlane = (lane & 1);

    __shared__ float fin[SN];
    __shared__ int   ecap_sh;

    // Extended labels: state s = KS*lane + j ; parity of s = parity of lane+j
    int  cls[KS];
    bool valid[KS];
    #pragma unroll
    for (int j = 0; j < KS; ++j) {
        int s = KS * lane + j;
        valid[j] = (s < SN);
        int c = BLANK;
        if (valid[j] && (s & 1)) c = labels[b * LN + (s >> 1)];
        cls[j] = valid[j] ? c : 0;
    }
    int cu2 = __shfl_up_sync(FULL, cls[KS - 2], 1);
    int cu1 = __shfl_up_sync(FULL, cls[KS - 1], 1);
    bool alw[KS];
    #pragma unroll
    for (int j = 0; j < KS; ++j) {
        int s   = KS * lane + j;
        int cm2 = (j >= 2) ? cls[j - 2] : ((j == 1) ? cu1 : cu2);
        alw[j] = valid[j] && (s >= 2) && (cls[j] != BLANK) && (cls[j] != cm2);
    }

    // Label classes gathered per lane (blank loaded once, broadcast):
    //   even lane: labels at j = 1, 3 (third slot duplicates blank)
    //   odd  lane: labels at j = 0, 2, 4
    const int lc0 = oddlane ? cls[0] : cls[1];
    const int lc1 = oddlane ? cls[2] : cls[3];
    const int lc2 = oddlane ? cls[4] : BLANK;

    const float* base  = y_pred + (size_t)b * TN * CN;
    const int    T_eff = in_len[b];

    // t = 0
    float a[KS];
    #pragma unroll
    for (int j = 0; j < KS; ++j) {
        int s = KS * lane + j;
        a[j] = (s < 2) ? (base[cls[j]] + EPSV) : 0.0f;
    }
    if (T_eff == 1) {
        #pragma unroll
        for (int j = 0; j < KS; ++j)
            if (valid[j]) fin[KS * lane + j] = a[j];
        if (lane == 0) ecap_sh = 0;
    }

    // Register prefetch ring: raw probs for rows t = 1..PD
    float prb[PD], pr0[PD], pr1[PD], pr2[PD];
    #pragma unroll
    for (int i = 0; i < PD; ++i) {
        const float* r = base + (size_t)(1 + i) * CN;
        prb[i] = __ldg(r + BLANK);
        pr0[i] = __ldg(r + lc0);
        pr1[i] = __ldg(r + lc1);
        pr2[i] = __ldg(r + lc2);
    }

    int   E = 0, pend_e = 0;
    float pend_sc = 1.0f;

    #pragma unroll 8
    for (int t = 1; t < TN; ++t) {
        const int slot = (t - 1) & (PD - 1);

        // Halo from previous alpha (register-only)
        float h1 = __shfl_up_sync(FULL, a[KS - 1], 1);
        float h2 = __shfl_up_sync(FULL, a[KS - 2], 1);
        if (lane == 0) { h1 = 0.0f; h2 = 0.0f; }

        float sc512 = 512.0f * pend_sc;
        float epssc = (512.0f * EPSV) * pend_sc;
        E += pend_e; pend_e = 0; pend_sc = 1.0f;

        // pe values from the register ring (scoreboard wait lands here)
        float pe_b = fmaf(prb[slot], sc512, epssc);
        float pe_0 = fmaf(pr0[slot], sc512, epssc);
        float pe_1 = fmaf(pr1[slot], sc512, epssc);
        float pe_2 = fmaf(pr2[slot], sc512, epssc);

        // Refill this slot with row t+PD (clamped; surplus values unused)
        {
            int st = t + PD; if (st > TN - 1) st = TN - 1;
            const float* r = base + (size_t)st * CN;
            prb[slot] = __ldg(r + BLANK);
            pr0[slot] = __ldg(r + lc0);
            pr1[slot] = __ldg(r + lc1);
            pr2[slot] = __ldg(r + lc2);
        }

        float pe[KS];
        pe[0] = oddlane ? pe_0 : pe_b;
        pe[1] = oddlane ? pe_b : pe_0;
        pe[2] = oddlane ? pe_1 : pe_b;
        pe[3] = oddlane ? pe_b : pe_1;
        pe[4] = oddlane ? pe_2 : pe_b;
        #pragma unroll
        for (int j = 0; j < KS; ++j)
            if (!valid[j]) pe[j] = 0.0f;

        float n0 = (a[0] + h1   + (alw[0] ? h2   : 0.0f)) * pe[0];
        float n1 = (a[1] + a[0] + (alw[1] ? h1   : 0.0f)) * pe[1];
        float n2 = (a[2] + a[1] + (alw[2] ? a[0] : 0.0f)) * pe[2];
        float n3 = (a[3] + a[2] + (alw[3] ? a[1] : 0.0f)) * pe[3];
        float n4 = (a[4] + a[3] + (alw[4] ? a[2] : 0.0f)) * pe[4];
        a[0] = n0; a[1] = n1; a[2] = n2; a[3] = n3; a[4] = n4;

        if ((t & 7) == 0) {
            unsigned u = __float_as_uint(a[0]);
            u = max(u, __float_as_uint(a[1]));
            u = max(u, __float_as_uint(a[2]));
            u = max(u, __float_as_uint(a[3]));
            u = max(u, __float_as_uint(a[4]));
            u = __reduce_max_sync(FULL, u);
            int e = (int)(u >> 23) - 127;
            pend_e  = e;
            pend_sc = __uint_as_float((unsigned)(127 - e) << 23);  // 2^-e exact
        }

        if (t == T_eff - 1) {
            #pragma unroll
            for (int j = 0; j < KS; ++j)
                if (valid[j]) fin[KS * lane + j] = a[j];
            if (lane == 0) ecap_sh = E;
        }
    }
    __syncwarp();

    if (lane == 0) {
        int ll = lab_len[b];
        int i1 = 2 * ll;
        int i2 = 2 * ll - 1;
        if (i1 < 0) i1 += SN;
        if (i2 < 0) i2 += SN;
        float x = fin[i1] + fin[i2];
        // stored = true * 2^(9*(T_eff-1) - ecap)
        out[b] = -logf(x) + ((float)(9 * (T_eff - 1) - ecap_sh)) * LN2F;
    }
}

extern "C" void kernel_launch(void* const* d_in, const int* in_sizes, int n_in,
                              void* d_out, int out_size)
{
    const int*   y_true       = (const int*)d_in[0];
    const float* y_pred       = (const float*)d_in[1];
    const int*   input_length = (const int*)d_in[2];
    const int*   label_length = (const int*)d_in[3];
    float*       out          = (float*)d_out;

    ctc_ldg_kernel<<<BN, 32>>>(y_true, y_pred, input_length, label_length, out);
}

// round 12
// speedup vs baseline: 1.3558x; 1.3558x over previous
#include <cuda_runtime.h>
#include <math.h>

// B=256, T=512, C=512, L=64
#define BN 256
#define TN 512
#define CN 512
#define LN 64
#define SN 129              // 2L+1
#define BLANK 511
#define EPSV 1e-7f
#define RS 32               // ring slots (31 groups in flight; smem is tiny)
#define PKW 68              // packed row stride (65 used, padded)
#define KS 5                // states per lane
#define LN2F 0.6931471805599453f
#define FULL 0xffffffffu

// CTC forward DP: one warp per batch element. Instead of streaming full
// 2KB class rows, each step copies ONLY the 65 reachable probabilities
// (64 label classes + blank) into a packed smem row via per-lane 4B
// cp.async gathers (lane k fetches classes lab[k], lab[k+32]; lane 0 also
// the blank). DP states read packed[s odd ? s>>1 : 64]. 32-deep ring.
// Linear-space recursion + exact power-of-2 renorm (identical arithmetic
// and order to previous rounds; rel_err unchanged).
__global__ __launch_bounds__(32, 8)
void ctc_pack_kernel(const int* __restrict__ labels,     // [B, L]
                     const float* __restrict__ y_pred,   // [B, T, C]
                     const int* __restrict__ in_len,     // [B, 1]
                     const int* __restrict__ lab_len,    // [B, 1]
                     float* __restrict__ out)            // [B, 1]
{
    const int b    = blockIdx.x;
    const int lane = threadIdx.x;
    const bool oddlane = (lane & 1);

    __shared__ __align__(16) float packed[RS][PKW];   // ~8.7KB ring
    __shared__ float fin[SN];
    __shared__ int   ecap_sh;

    // Extended labels: state s = KS*lane + j ; parity of s = parity of lane+j
    int  cls[KS];
    bool valid[KS];
    #pragma unroll
    for (int j = 0; j < KS; ++j) {
        int s = KS * lane + j;
        valid[j] = (s < SN);
        int c = BLANK;
        if (valid[j] && (s & 1)) c = labels[b * LN + (s >> 1)];
        cls[j] = valid[j] ? c : 0;
    }
    int cu2 = __shfl_up_sync(FULL, cls[KS - 2], 1);
    int cu1 = __shfl_up_sync(FULL, cls[KS - 1], 1);
    bool alw[KS];
    #pragma unroll
    for (int j = 0; j < KS; ++j) {
        int s   = KS * lane + j;
        int cm2 = (j >= 2) ? cls[j - 2] : ((j == 1) ? cu1 : cu2);
        alw[j] = valid[j] && (s >= 2) && (cls[j] != BLANK) && (cls[j] != cm2);
    }

    // Packed-row gather indices for this lane's odd (label) states:
    //   odd  lane: labels at j = 0, 2, 4 -> positions (5l)/2, (5l+2)/2, (5l+4)/2
    //   even lane: labels at j = 1, 3    -> positions (5l+1)/2, (5l+3)/2 (+blank dup)
    const int i0 = oddlane ? ((5 * lane) >> 1)     : ((5 * lane + 1) >> 1);
    const int i1 = oddlane ? ((5 * lane + 2) >> 1) : ((5 * lane + 3) >> 1);
    const int i2 = oddlane ? ((5 * lane + 4) >> 1) : 64;
    // (positions >= 64 only occur for invalid states; clamp into row)
    const int g0 = (i0 < 64) ? i0 : 64;
    const int g1 = (i1 < 64) ? i1 : 64;
    const int g2 = (i2 < 64) ? i2 : 64;

    // Copy-source classes for this lane (packed positions lane, lane+32)
    const int cpc0 = labels[b * LN + lane];
    const int cpc1 = labels[b * LN + lane + 32];

    const float* base  = y_pred + (size_t)b * TN * CN;
    const int    T_eff = in_len[b];

    // t = 0
    float a[KS];
    #pragma unroll
    for (int j = 0; j < KS; ++j) {
        int s = KS * lane + j;
        a[j] = (s < 2) ? (base[cls[j]] + EPSV) : 0.0f;
    }
    if (T_eff == 1) {
        #pragma unroll
        for (int j = 0; j < KS; ++j)
            if (valid[j]) fin[KS * lane + j] = a[j];
        if (lane == 0) ecap_sh = 0;
    }

    // Prologue: packed rows 1..RS-1, one commit group each
    #pragma unroll 4
    for (int st = 1; st < RS; ++st) {
        const float* r = base + (size_t)st * CN;
        unsigned d0 = (unsigned)__cvta_generic_to_shared(&packed[st & (RS - 1)][lane]);
        unsigned d1 = (unsigned)__cvta_generic_to_shared(&packed[st & (RS - 1)][lane + 32]);
        asm volatile("cp.async.ca.shared.global [%0], [%1], 4;" :: "r"(d0), "l"(r + cpc0));
        asm volatile("cp.async.ca.shared.global [%0], [%1], 4;" :: "r"(d1), "l"(r + cpc1));
        if (lane == 0) {
            unsigned d2 = (unsigned)__cvta_generic_to_shared(&packed[st & (RS - 1)][64]);
            asm volatile("cp.async.ca.shared.global [%0], [%1], 4;" :: "r"(d2), "l"(r + BLANK));
        }
        asm volatile("cp.async.commit_group;");
    }

    int   E = 0, pend_e = 0;
    float pend_sc = 1.0f;

    #pragma unroll 8
    for (int t = 1; t < TN; ++t) {
        // Halo from previous alpha (register-only; overlaps the wait)
        float h1 = __shfl_up_sync(FULL, a[KS - 1], 1);
        float h2 = __shfl_up_sync(FULL, a[KS - 2], 1);
        if (lane == 0) { h1 = 0.0f; h2 = 0.0f; }

        float sc512 = 512.0f * pend_sc;
        float epssc = (512.0f * EPSV) * pend_sc;
        E += pend_e; pend_e = 0; pend_sc = 1.0f;

        asm volatile("cp.async.wait_group %0;" :: "n"(RS - 2)); // row t done
        __syncwarp();

        // Gather from packed row (blank broadcast + <=3 label positions)
        const float* row = packed[t & (RS - 1)];
        float pb  = row[64];
        float pl0 = row[g0];
        float pl1 = row[g1];
        float pl2 = row[g2];

        // Refill slot (t-1)&(RS-1) with packed row t+RS-1 (WAR-safe)
        {
            int st = t + RS - 1;
            int wsl = (t - 1) & (RS - 1);
            if (st < TN) {
                const float* r = base + (size_t)st * CN;
                unsigned d0 = (unsigned)__cvta_generic_to_shared(&packed[wsl][lane]);
                unsigned d1 = (unsigned)__cvta_generic_to_shared(&packed[wsl][lane + 32]);
                asm volatile("cp.async.ca.shared.global [%0], [%1], 4;" :: "r"(d0), "l"(r + cpc0));
                asm volatile("cp.async.ca.shared.global [%0], [%1], 4;" :: "r"(d1), "l"(r + cpc1));
                if (lane == 0) {
                    unsigned d2 = (unsigned)__cvta_generic_to_shared(&packed[wsl][64]);
                    asm volatile("cp.async.ca.shared.global [%0], [%1], 4;" :: "r"(d2), "l"(r + BLANK));
                }
            }
            asm volatile("cp.async.commit_group;");  // uniform group count
        }

        float pe_b = fmaf(pb,  sc512, epssc);
        float pe_0 = fmaf(pl0, sc512, epssc);
        float pe_1 = fmaf(pl1, sc512, epssc);
        float pe_2 = fmaf(pl2, sc512, epssc);

        float pe[KS];
        pe[0] = oddlane ? pe_0 : pe_b;
        pe[1] = oddlane ? pe_b : pe_0;
        pe[2] = oddlane ? pe_1 : pe_b;
        pe[3] = oddlane ? pe_b : pe_1;
        pe[4] = oddlane ? pe_2 : pe_b;
        #pragma unroll
        for (int j = 0; j < KS; ++j)
            if (!valid[j]) pe[j] = 0.0f;

        float n0 = (a[0] + h1   + (alw[0] ? h2   : 0.0f)) * pe[0];
        float n1 = (a[1] + a[0] + (alw[1] ? h1   : 0.0f)) * pe[1];
        float n2 = (a[2] + a[1] + (alw[2] ? a[0] : 0.0f)) * pe[2];
        float n3 = (a[3] + a[2] + (alw[3] ? a[1] : 0.0f)) * pe[3];
        float n4 = (a[4] + a[3] + (alw[4] ? a[2] : 0.0f)) * pe[4];
        a[0] = n0; a[1] = n1; a[2] = n2; a[3] = n3; a[4] = n4;

        if ((t & 7) == 0) {
            unsigned u = __float_as_uint(a[0]);
            u = max(u, __float_as_uint(a[1]));
            u = max(u, __float_as_uint(a[2]));
            u = max(u, __float_as_uint(a[3]));
            u = max(u, __float_as_uint(a[4]));
            u = __reduce_max_sync(FULL, u);
            int e = (int)(u >> 23) - 127;
            pend_e  = e;
            pend_sc = __uint_as_float((unsigned)(127 - e) << 23);  // 2^-e exact
        }

        if (t == T_eff - 1) {
            #pragma unroll
            for (int j = 0; j < KS; ++j)
                if (valid[j]) fin[KS * lane + j] = a[j];
            if (lane == 0) ecap_sh = E;
        }
    }
    __syncwarp();

    if (lane == 0) {
        int ll = lab_len[b];
        int i1f = 2 * ll;
        int i2f = 2 * ll - 1;
        if (i1f < 0) i1f += SN;
        if (i2f < 0) i2f += SN;
        float x = fin[i1f] + fin[i2f];
        // stored = true * 2^(9*(T_eff-1) - ecap)
        out[b] = -logf(x) + ((float)(9 * (T_eff - 1) - ecap_sh)) * LN2F;
    }
}

extern "C" void kernel_launch(void* const* d_in, const int* in_sizes, int n_in,
                              void* d_out, int out_size)
{
    const int*   y_true       = (const int*)d_in[0];
    const float* y_pred       = (const float*)d_in[1];
    const int*   input_length = (const int*)d_in[2];
    const int*   label_length = (const int*)d_in[3];
    float*       out          = (float*)d_out;

    ctc_pack_kernel<<<BN, 32>>>(y_true, y_pred, input_length, label_length, out);
}

// round 13
// speedup vs baseline: 1.9489x; 1.4374x over previous
#include <cuda_runtime.h>
#include <math.h>

// B=256, T=512, C=512, L=64
#define BN 256
#define TN 512
#define CN 512
#define LN 64
#define SN 129              // 2L+1
#define BLANK 511
#define EPSV 1e-7f
#define RS 16               // row-ring slots (ring indexed t & 15)
#define KS 5                // states per lane
#define LN2F 0.6931471805599453f
#define FULL 0xffffffffu

// CTC forward DP: one warp per batch element (round-10 winner skeleton),
// with TWO time steps fused per loop iteration: one wait_group + one
// syncwarp + one commit group (carrying two 2KB rows) per pair of steps.
// 7 groups x 2 rows = 14 rows in flight (same DRAM-latency cover as
// round 10). Blank-dedup smem gather; alpha in registers (5/lane);
// neighbors via shfl. Linear-space recursion + exact power-of-2 renorm
// (arithmetic and renorm cadence identical to round 10).
__global__ __launch_bounds__(32, 4)
void ctc_fuse2_kernel(const int* __restrict__ labels,     // [B, L]
                      const float* __restrict__ y_pred,   // [B, T, C]
                      const int* __restrict__ in_len,     // [B, 1]
                      const int* __restrict__ lab_len,    // [B, 1]
                      float* __restrict__ out)            // [B, 1]
{
    const int b    = blockIdx.x;
    const int lane = threadIdx.x;
    const bool oddlane = (lane & 1);

    __shared__ __align__(16) float rows[RS][CN];   // 32KB ring
    __shared__ float fin[SN];
    __shared__ int   ecap_sh;

    // Extended labels: state s = KS*lane + j ; parity of s = parity of lane+j
    int  cls[KS];
    bool valid[KS];
    #pragma unroll
    for (int j = 0; j < KS; ++j) {
        int s = KS * lane + j;
        valid[j] = (s < SN);
        int c = BLANK;
        if (valid[j] && (s & 1)) c = labels[b * LN + (s >> 1)];
        cls[j] = valid[j] ? c : 0;
    }
    int cu2 = __shfl_up_sync(FULL, cls[KS - 2], 1);
    int cu1 = __shfl_up_sync(FULL, cls[KS - 1], 1);
    bool alw[KS];
    #pragma unroll
    for (int j = 0; j < KS; ++j) {
        int s   = KS * lane + j;
        int cm2 = (j >= 2) ? cls[j - 2] : ((j == 1) ? cu1 : cu2);
        alw[j] = valid[j] && (s >= 2) && (cls[j] != BLANK) && (cls[j] != cm2);
    }

    // Label-gather classes (blank handled via one broadcast load)
    const int lc0 = oddlane ? cls[0] : cls[1];
    const int lc1 = oddlane ? cls[2] : cls[3];
    const int lc2 = oddlane ? cls[4] : BLANK;

    const float* base  = y_pred + (size_t)b * TN * CN;
    const int    T_eff = in_len[b];

    // t = 0
    float a[KS];
    #pragma unroll
    for (int j = 0; j < KS; ++j) {
        int s = KS * lane + j;
        a[j] = (s < 2) ? (base[cls[j]] + EPSV) : 0.0f;
    }
    if (T_eff == 1) {
        #pragma unroll
        for (int j = 0; j < KS; ++j)
            if (valid[j]) fin[KS * lane + j] = a[j];
        if (lane == 0) ecap_sh = 0;
    }

    // cp.async helper for one full row into its slot
    #define CPROW(ST)                                                          \
        do {                                                                   \
            _Pragma("unroll")                                                  \
            for (int k = 0; k < 4; ++k) {                                      \
                unsigned dst = (unsigned)__cvta_generic_to_shared(             \
                    &rows[(ST) & (RS - 1)][lane * 4 + k * 128]);               \
                const float* src = base + (size_t)(ST) * CN + lane * 4 + k * 128; \
                asm volatile("cp.async.cg.shared.global [%0], [%1], 16;"       \
                             :: "r"(dst), "l"(src));                           \
            }                                                                  \
        } while (0)

    // Prologue: 8 groups, group g carries rows 2g+1, 2g+2 (rows 1..16)
    #pragma unroll
    for (int g = 0; g < 8; ++g) {
        CPROW(2 * g + 1);
        CPROW(2 * g + 2);
        asm volatile("cp.async.commit_group;");
    }

    int   E = 0, pend_e = 0;
    float pend_sc = 1.0f;

    // Gather + DP step macro (step for time t, pe scale sc/ep, row pointer R)
    #define GATHER(R, PB, P0, P1, P2)                                          \
        float PB = (R)[BLANK];                                                 \
        float P0 = (R)[lc0];                                                   \
        float P1 = (R)[lc1];                                                   \
        float P2 = (R)[lc2];

    #define STEP(PB, P0, P1, P2, SC, EP)                                       \
        do {                                                                   \
            float h1 = __shfl_up_sync(FULL, a[KS - 1], 1);                     \
            float h2 = __shfl_up_sync(FULL, a[KS - 2], 1);                     \
            if (lane == 0) { h1 = 0.0f; h2 = 0.0f; }                           \
            float pe_b = fmaf(PB, SC, EP);                                     \
            float pe_0 = fmaf(P0, SC, EP);                                     \
            float pe_1 = fmaf(P1, SC, EP);                                     \
            float pe_2 = fmaf(P2, SC, EP);                                     \
            float pe[KS];                                                      \
            pe[0] = oddlane ? pe_0 : pe_b;                                     \
            pe[1] = oddlane ? pe_b : pe_0;                                     \
            pe[2] = oddlane ? pe_1 : pe_b;                                     \
            pe[3] = oddlane ? pe_b : pe_1;                                     \
            pe[4] = oddlane ? pe_2 : pe_b;                                     \
            _Pragma("unroll")                                                  \
            for (int j = 0; j < KS; ++j) if (!valid[j]) pe[j] = 0.0f;          \
            float n0 = (a[0] + h1   + (alw[0] ? h2   : 0.0f)) * pe[0];         \
            float n1 = (a[1] + a[0] + (alw[1] ? h1   : 0.0f)) * pe[1];         \
            float n2 = (a[2] + a[1] + (alw[2] ? a[0] : 0.0f)) * pe[2];         \
            float n3 = (a[3] + a[2] + (alw[3] ? a[1] : 0.0f)) * pe[3];         \
            float n4 = (a[4] + a[3] + (alw[4] ? a[2] : 0.0f)) * pe[4];         \
            a[0] = n0; a[1] = n1; a[2] = n2; a[3] = n3; a[4] = n4;             \
        } while (0)

    #define FINCHK(T)                                                          \
        if ((T) == T_eff - 1) {                                                \
            _Pragma("unroll")                                                  \
            for (int j = 0; j < KS; ++j)                                       \
                if (valid[j]) fin[KS * lane + j] = a[j];                       \
            if (lane == 0) ecap_sh = E;                                        \
        }

    #pragma unroll 4
    for (int pr = 0; pr < 255; ++pr) {
        const int t0 = 2 * pr + 1;
        const int t1 = t0 + 1;

        // Apply pending renorm (only ever set after even t)
        float sc512 = 512.0f * pend_sc;
        float epssc = (512.0f * EPSV) * pend_sc;
        E += pend_e; pend_e = 0; pend_sc = 1.0f;

        // wait<=7: with 8+pr groups committed, groups 0..pr complete ->
        // rows up to 2pr+2 = t1 resident
        asm volatile("cp.async.wait_group %0;" :: "n"(7));
        __syncwarp();

        // Both gathers up front (row t1's LDS latency hides under step t0)
        const float* r0 = rows[t0 & (RS - 1)];
        const float* r1 = rows[t1 & (RS - 1)];
        GATHER(r0, pb0, pl00, pl01, pl02);
        GATHER(r1, pb1, pl10, pl11, pl12);

        // Refill: one group carrying rows t0+16, t1+16 (guard each)
        {
            int s0 = t0 + RS, s1 = t1 + RS;
            if (s0 < TN) CPROW(s0);
            if (s1 < TN) CPROW(s1);
            asm volatile("cp.async.commit_group;");
        }

        // Step t0 (odd t never triggers renorm)
        STEP(pb0, pl00, pl01, pl02, sc512, epssc);
        FINCHK(t0);

        // Step t1 (no pending renorm between t0 and t1)
        STEP(pb1, pl10, pl11, pl12, 512.0f, 512.0f * EPSV);

        if ((t1 & 7) == 0) {
            unsigned u = __float_as_uint(a[0]);
            u = max(u, __float_as_uint(a[1]));
            u = max(u, __float_as_uint(a[2]));
            u = max(u, __float_as_uint(a[3]));
            u = max(u, __float_as_uint(a[4]));
            u = __reduce_max_sync(FULL, u);
            int e = (int)(u >> 23) - 127;
            pend_e  = e;
            pend_sc = __uint_as_float((unsigned)(127 - e) << 23);  // 2^-e exact
        }
        FINCHK(t1);
    }

    // Epilogue: t = 511 (row 511 loaded by refill at pr=247, slot 15)
    {
        const int t = TN - 1;
        float sc512 = 512.0f * pend_sc;
        float epssc = (512.0f * EPSV) * pend_sc;
        E += pend_e; pend_e = 0; pend_sc = 1.0f;

        asm volatile("cp.async.wait_group 0;");
        __syncwarp();

        const float* r0 = rows[t & (RS - 1)];
        GATHER(r0, pbe, ple0, ple1, ple2);
        STEP(pbe, ple0, ple1, ple2, sc512, epssc);
        FINCHK(t);
    }
    __syncwarp();

    if (lane == 0) {
        int ll = lab_len[b];
        int i1 = 2 * ll;
        int i2 = 2 * ll - 1;
        if (i1 < 0) i1 += SN;
        if (i2 < 0) i2 += SN;
        float x = fin[i1] + fin[i2];
        // stored = true * 2^(9*(T_eff-1) - ecap)
        out[b] = -logf(x) + ((float)(9 * (T_eff - 1) - ecap_sh)) * LN2F;
    }
}

extern "C" void kernel_launch(void* const* d_in, const int* in_sizes, int n_in,
                              void* d_out, int out_size)
{
    const int*   y_true       = (const int*)d_in[0];
    const float* y_pred       = (const float*)d_in[1];
    const int*   input_length = (const int*)d_in[2];
    const int*   label_length = (const int*)d_in[3];
    float*       out          = (float*)d_out;

    ctc_fuse2_kernel<<<BN, 32>>>(y_true, y_pred, input_length, label_length, out);
}